// round 1
// baseline (speedup 1.0000x reference)
#include <cuda_runtime.h>
#include <cuda_bf16.h>

#define N_RELS 64

// Branchless sparsemax for d=3. Faithful to the reference:
//   ksup = sum_k [1 + k*zs_k > cs_k],  tau = (cs[ksup-1] - 1)/ksup
static __device__ __forceinline__ void sparsemax3(float x0, float x1, float x2,
                                                  float &o0, float &o1, float &o2) {
    // 3-element descending sort network
    float a  = fmaxf(x0, x1), b = fminf(x0, x1);
    float z0 = fmaxf(a, x2);
    float t  = fminf(a, x2);
    float z1 = fmaxf(b, t);
    float z2 = fminf(b, t);            // z0 >= z1 >= z2
    float cs1 = z0 + z1;
    float cs2 = cs1 + z2;
    // k=1 support is always true (1 + z0 > z0)
    int s2 = (1.0f + 2.0f * z1) > cs1;
    int s3 = (1.0f + 3.0f * z2) > cs2;
    int k  = 1 + s2 + s3;              // matches jnp.sum(support)
    float csk = (k == 3) ? cs2 : ((k == 2) ? cs1 : z0);  // take_along(cs, k-1)
    float rk  = (k == 3) ? (1.0f / 3.0f) : ((k == 2) ? 0.5f : 1.0f);
    float tau = (csk - 1.0f) * rk;
    o0 = fmaxf(x0 - tau, 0.0f);
    o1 = fmaxf(x1 - tau, 0.0f);
    o2 = fmaxf(x2 - tau, 0.0f);
}

static __device__ __forceinline__ void row_compute(
    float p0, float p1, float p2,
    float h0, float h1, float h2,
    const float *Mr, const float *Br,
    float zeps, float sf,
    float &a0, float &a1, float &a2)
{
    // c = M[rel] @ child   (einsum 'ij,j->i', row-major M)
    float c0 = Mr[0] * h0 + Mr[1] * h1 + Mr[2] * h2;
    float c1 = Mr[3] * h0 + Mr[4] * h1 + Mr[5] * h2;
    float c2 = Mr[6] * h0 + Mr[7] * h1 + Mr[8] * h2;
    sparsemax3(c0, c1, c2, c0, c1, c2);
    sparsemax3(c0, c1, c2, c0, c1, c2);   // faithful re-application
    sparsemax3(p0, p1, p2, p0, p1, p2);

    float b0 = Br[0], b1 = Br[1], b2 = Br[2];
    a0 = (1.0f - b0) * p0 + b0 * c0;
    a1 = (1.0f - b1) * p1 + b1 * c1;
    a2 = (1.0f - b2) * p2 + b2 * c2;

    // scale(): entropy of clamped normalized mixture
    float w0 = fmaxf(p0 + c0, zeps);
    float w1 = fmaxf(p1 + c1, zeps);
    float w2 = fmaxf(p2 + c2, zeps);
    float inv = __fdividef(1.0f, w0 + w1 + w2);
    w0 *= inv; w1 *= inv; w2 *= inv;
    float ent = -(w0 * __logf(w0) + w1 * __logf(w1) + w2 * __logf(w2));

    // cosine similarity between p and c
    float dot = p0 * c0 + p1 * c1 + p2 * c2;
    float pp  = p0 * p0 + p1 * p1 + p2 * p2;
    float cc  = c0 * c0 + c1 * c1 + c2 * c2;
    float nrm = fmaxf(__fsqrt_rn(pp) * __fsqrt_rn(cc), 1e-10f);
    float cosv  = 0.1f + __fdividef(dot, nrm);
    float scale = __fdividef(sf * cosv, ent);

    a0 = fmaxf(a0 * scale, 0.001f);
    a1 = fmaxf(a1 * scale, 0.001f);
    a2 = fmaxf(a2 * scale, 0.001f);
}

__global__ void __launch_bounds__(256)
alpha_kernel(const float *__restrict__ prnt,
             const float *__restrict__ child,
             const float *__restrict__ Mg,
             const float *__restrict__ betag,
             const float *__restrict__ zeps_p,
             const float *__restrict__ sf_p,
             const int *__restrict__ rels,
             float *__restrict__ out,
             int n, int nquads)
{
    __shared__ float sM[N_RELS * 9];
    __shared__ float sB[N_RELS * 3];
    for (int i = threadIdx.x; i < N_RELS * 9; i += blockDim.x) sM[i] = Mg[i];
    for (int i = threadIdx.x; i < N_RELS * 3; i += blockDim.x) sB[i] = betag[i];
    __syncthreads();

    const float zeps = __ldg(zeps_p);
    const float sf   = __ldg(sf_p);

    int q = blockIdx.x * blockDim.x + threadIdx.x;

    if (q < nquads) {
        // 4 rows per thread: 12 floats = 3 aligned float4 per tensor
        const float4 *p4 = reinterpret_cast<const float4 *>(prnt)  + (size_t)q * 3;
        const float4 *c4 = reinterpret_cast<const float4 *>(child) + (size_t)q * 3;
        float4 pA = p4[0], pB = p4[1], pC = p4[2];
        float4 cA = c4[0], cB = c4[1], cC = c4[2];
        int4 r4 = reinterpret_cast<const int4 *>(rels)[q];

        float pv[12] = {pA.x, pA.y, pA.z, pA.w, pB.x, pB.y, pB.z, pB.w,
                        pC.x, pC.y, pC.z, pC.w};
        float cv[12] = {cA.x, cA.y, cA.z, cA.w, cB.x, cB.y, cB.z, cB.w,
                        cC.x, cC.y, cC.z, cC.w};
        int rr[4] = {r4.x, r4.y, r4.z, r4.w};
        float ov[12];

#pragma unroll
        for (int i = 0; i < 4; i++) {
            const float *Mr = &sM[rr[i] * 9];
            const float *Br = &sB[rr[i] * 3];
            row_compute(pv[3 * i], pv[3 * i + 1], pv[3 * i + 2],
                        cv[3 * i], cv[3 * i + 1], cv[3 * i + 2],
                        Mr, Br, zeps, sf,
                        ov[3 * i], ov[3 * i + 1], ov[3 * i + 2]);
        }

        float4 *o4 = reinterpret_cast<float4 *>(out) + (size_t)q * 3;
        o4[0] = make_float4(ov[0], ov[1], ov[2],  ov[3]);
        o4[1] = make_float4(ov[4], ov[5], ov[6],  ov[7]);
        o4[2] = make_float4(ov[8], ov[9], ov[10], ov[11]);
    }

    // scalar tail (n % 4 rows) — empty for N = 8,000,000 but kept general
    int rem = n - nquads * 4;
    if (q < rem) {
        int i = nquads * 4 + q;
        const float *Mr = &sM[rels[i] * 9];
        const float *Br = &sB[rels[i] * 3];
        float a0, a1, a2;
        row_compute(prnt[3 * i], prnt[3 * i + 1], prnt[3 * i + 2],
                    child[3 * i], child[3 * i + 1], child[3 * i + 2],
                    Mr, Br, zeps, sf, a0, a1, a2);
        out[3 * i] = a0; out[3 * i + 1] = a1; out[3 * i + 2] = a2;
    }
}

extern "C" void kernel_launch(void* const* d_in, const int* in_sizes, int n_in,
                              void* d_out, int out_size) {
    // metadata order: prnt_probs, child_probs, M, beta, z_epsilon, scale_factor, rels, var_sfx
    const float *prnt  = (const float *)d_in[0];
    const float *child = (const float *)d_in[1];
    const float *Mg    = (const float *)d_in[2];
    const float *betag = (const float *)d_in[3];
    const float *zeps  = (const float *)d_in[4];
    const float *sf    = (const float *)d_in[5];
    const int   *rels  = (const int *)d_in[6];
    float *out = (float *)d_out;

    int n = in_sizes[6];          // number of edges
    int nquads = n / 4;
    int work = nquads > 0 ? nquads : 1;
    int threads = 256;
    int blocks = (work + threads - 1) / threads;

    alpha_kernel<<<blocks, threads>>>(prnt, child, Mg, betag, zeps, sf, rels,
                                      out, n, nquads);
}

// round 2
// speedup vs baseline: 1.0563x; 1.0563x over previous
#include <cuda_runtime.h>
#include <cuda_bf16.h>

#define N_RELS 64
#define REL_STRIDE4 5   // 5 float4 per relation = 80B (bank-friendly stride)

// Branchless sparsemax for d=3, reduced-op form.
// Faithful to: ksup = sum_k [1 + k*zs_k > cs_k], tau = (cs[ksup-1]-1)/ksup
// using cs2 = sum (sort-invariant), z0 = max, z2 = min, z1 = sum-max-min,
// s2: 1+2z1 > z0+z1  <=>  1+z1 > z0 ;  s3: 1+3z2 > sum.  (s3 => s2)
static __device__ __forceinline__ void sparsemax3(float x0, float x1, float x2,
                                                  float &o0, float &o1, float &o2) {
    float mx  = fmaxf(fmaxf(x0, x1), x2);
    float mn  = fminf(fminf(x0, x1), x2);
    float sum = x0 + x1 + x2;
    float z1  = sum - mx - mn;
    bool s2 = (1.0f + z1) > mx;
    bool s3 = (1.0f + 3.0f * mn) > sum;
    float csk = mx + (s2 ? z1 : 0.0f) + (s3 ? mn : 0.0f);  // cs[k-1]
    float rk  = s3 ? (1.0f / 3.0f) : (s2 ? 0.5f : 1.0f);   // 1/k
    float tau = (csk - 1.0f) * rk;
    o0 = fmaxf(x0 - tau, 0.0f);
    o1 = fmaxf(x1 - tau, 0.0f);
    o2 = fmaxf(x2 - tau, 0.0f);
}

static __device__ __forceinline__ void row_compute(
    float p0, float p1, float p2,
    float h0, float h1, float h2,
    const float4 *__restrict__ relp,
    float zeps, float sf,
    float &a0, float &a1, float &a2)
{
    float4 m0 = relp[0];
    float4 m1 = relp[1];
    float4 m2 = relp[2];
    float4 bb = relp[3];

    // c = M[rel] @ child
    float c0 = m0.x * h0 + m0.y * h1 + m0.z * h2;
    float c1 = m1.x * h0 + m1.y * h1 + m1.z * h2;
    float c2 = m2.x * h0 + m2.y * h1 + m2.z * h2;
    sparsemax3(c0, c1, c2, c0, c1, c2);
    // (second sparsemax is an exact identity on a simplex point — dropped)
    sparsemax3(p0, p1, p2, p0, p1, p2);

    a0 = (1.0f - bb.x) * p0 + bb.x * c0;
    a1 = (1.0f - bb.y) * p1 + bb.y * c1;
    a2 = (1.0f - bb.z) * p2 + bb.z * c2;

    // entropy of clamped normalized mixture (base-2, fold ln2 into the divide)
    float w0 = fmaxf(p0 + c0, zeps);
    float w1 = fmaxf(p1 + c1, zeps);
    float w2 = fmaxf(p2 + c2, zeps);
    float inv = __fdividef(1.0f, w0 + w1 + w2);
    w0 *= inv; w1 *= inv; w2 *= inv;
    float t2 = w0 * __log2f(w0) + w1 * __log2f(w1) + w2 * __log2f(w2); // negative
    // ent = -ln2 * t2

    float dot = p0 * c0 + p1 * c1 + p2 * c2;
    float pp  = p0 * p0 + p1 * p1 + p2 * p2;
    float cc  = c0 * c0 + c1 * c1 + c2 * c2;
    float nrm = fmaxf(__fsqrt_rn(pp) * __fsqrt_rn(cc), 1e-10f);
    // scale = sf * (0.1 + dot/nrm) / ent  ==  sf*(0.1*nrm + dot) / (nrm * -ln2 * t2)
    float num = sf * (0.1f * nrm + dot);
    float den = nrm * (-0.69314718056f) * t2;
    float scale = __fdividef(num, den);

    a0 = fmaxf(a0 * scale, 0.001f);
    a1 = fmaxf(a1 * scale, 0.001f);
    a2 = fmaxf(a2 * scale, 0.001f);
}

__global__ void __launch_bounds__(256)
alpha_kernel(const float *__restrict__ prnt,
             const float *__restrict__ child,
             const float *__restrict__ Mg,
             const float *__restrict__ betag,
             const float *__restrict__ zeps_p,
             const float *__restrict__ sf_p,
             const int *__restrict__ rels,
             float *__restrict__ out,
             int n, int nquads)
{
    // Per-rel record: m0,m1,m2 (padded rows of M), beta (padded), 1 pad float4.
    // 80B stride -> starting bank group cycles through all 8 4-bank groups.
    __shared__ float4 sRel[N_RELS * REL_STRIDE4];
    {
        float *sF = reinterpret_cast<float *>(sRel);
        for (int i = threadIdx.x; i < N_RELS * 12; i += blockDim.x) {
            int r = i / 12, j = i % 12;
            int row = j >> 2, c = j & 3;
            sF[r * 20 + j] = (c < 3) ? Mg[r * 9 + row * 3 + c] : 0.0f;
        }
        for (int i = threadIdx.x; i < N_RELS * 4; i += blockDim.x) {
            int r = i >> 2, c = i & 3;
            sF[r * 20 + 12 + c] = (c < 3) ? betag[r * 3 + c] : 0.0f;
        }
    }
    __syncthreads();

    const float zeps = __ldg(zeps_p);
    const float sf   = __ldg(sf_p);

    int q = blockIdx.x * blockDim.x + threadIdx.x;

    if (q < nquads) {
        const float4 *p4 = reinterpret_cast<const float4 *>(prnt)  + (size_t)q * 3;
        const float4 *c4 = reinterpret_cast<const float4 *>(child) + (size_t)q * 3;
        float4 pA = p4[0], pB = p4[1], pC = p4[2];
        float4 cA = c4[0], cB = c4[1], cC = c4[2];
        int4 r4 = reinterpret_cast<const int4 *>(rels)[q];

        float pv[12] = {pA.x, pA.y, pA.z, pA.w, pB.x, pB.y, pB.z, pB.w,
                        pC.x, pC.y, pC.z, pC.w};
        float cv[12] = {cA.x, cA.y, cA.z, cA.w, cB.x, cB.y, cB.z, cB.w,
                        cC.x, cC.y, cC.z, cC.w};
        int rr[4] = {r4.x, r4.y, r4.z, r4.w};
        float ov[12];

#pragma unroll
        for (int i = 0; i < 4; i++) {
            row_compute(pv[3 * i], pv[3 * i + 1], pv[3 * i + 2],
                        cv[3 * i], cv[3 * i + 1], cv[3 * i + 2],
                        &sRel[rr[i] * REL_STRIDE4], zeps, sf,
                        ov[3 * i], ov[3 * i + 1], ov[3 * i + 2]);
        }

        float4 *o4 = reinterpret_cast<float4 *>(out) + (size_t)q * 3;
        o4[0] = make_float4(ov[0], ov[1], ov[2],  ov[3]);
        o4[1] = make_float4(ov[4], ov[5], ov[6],  ov[7]);
        o4[2] = make_float4(ov[8], ov[9], ov[10], ov[11]);
    }

    // scalar tail (n % 4 rows) — empty for N = 8,000,000 but kept general
    int rem = n - nquads * 4;
    if (q < rem) {
        int i = nquads * 4 + q;
        float a0, a1, a2;
        row_compute(prnt[3 * i], prnt[3 * i + 1], prnt[3 * i + 2],
                    child[3 * i], child[3 * i + 1], child[3 * i + 2],
                    &sRel[rels[i] * REL_STRIDE4], zeps, sf, a0, a1, a2);
        out[3 * i] = a0; out[3 * i + 1] = a1; out[3 * i + 2] = a2;
    }
}

extern "C" void kernel_launch(void* const* d_in, const int* in_sizes, int n_in,
                              void* d_out, int out_size) {
    // metadata order: prnt_probs, child_probs, M, beta, z_epsilon, scale_factor, rels, var_sfx
    const float *prnt  = (const float *)d_in[0];
    const float *child = (const float *)d_in[1];
    const float *Mg    = (const float *)d_in[2];
    const float *betag = (const float *)d_in[3];
    const float *zeps  = (const float *)d_in[4];
    const float *sf    = (const float *)d_in[5];
    const int   *rels  = (const int *)d_in[6];
    float *out = (float *)d_out;

    int n = in_sizes[6];
    int nquads = n / 4;
    int work = nquads > 0 ? nquads : 1;
    int threads = 256;
    int blocks = (work + threads - 1) / threads;

    alpha_kernel<<<blocks, threads>>>(prnt, child, Mg, betag, zeps, sf, rels,
                                      out, n, nquads);
}